// round 12
// baseline (speedup 1.0000x reference)
#include <cuda_runtime.h>

#define TOK   4608      // n*H*W
#define NB    2
#define HH    48
#define WW    48
#define DM    256
#define NHEAD 4
#define EH    64
#define EPS   1e-6f

// ---------------- scratch ----------------
__device__ float g_scale[NB * DM];
__device__ float g_rfac [TOK];
__device__ float g_q   [NB * NHEAD * HH * WW * EH];
__device__ float g_k   [NB * NHEAD * HH * WW * EH];
__device__ float g_v   [NB * NHEAD * HH * WW * EH];
__device__ float g_o   [TOK * DM];

// ---------------- packed f32x2 helpers ----------------
__device__ __forceinline__ unsigned long long dupf(float x) {
    unsigned long long r;
    asm("mov.b64 %0,{%1,%2};" : "=l"(r) : "f"(x), "f"(x));
    return r;
}
__device__ __forceinline__ void ffma2(unsigned long long& c, unsigned long long a, unsigned long long b) {
    asm("fma.rn.f32x2 %0,%1,%2,%0;" : "+l"(c) : "l"(a), "l"(b));
}
__device__ __forceinline__ float2 unpk(unsigned long long v) {
    float2 r;
    asm("mov.b64 {%0,%1},%2;" : "=f"(r.x), "=f"(r.y) : "l"(v));
    return r;
}

// ---------------- K0: scale[b][c] = dot(cond[b], w_norm[c]) + 1 ----------------
__global__ void k_scale(const float* __restrict__ cond, const float* __restrict__ w_norm) {
    int b = blockIdx.x, c = threadIdx.x;
    const float4* cv = (const float4*)(cond + b * DM);
    const float4* wv = (const float4*)(w_norm + c * DM);
    float s = 0.f;
#pragma unroll 16
    for (int k = 0; k < DM / 4; k++) {
        float4 a = cv[k], w = wv[k];
        s += a.x * w.x + a.y * w.y + a.z * w.z + a.w * w.w;
    }
    g_scale[b * DM + c] = s + 1.f;
}

// ---------------- K1: per-token rsqrt(mean(x^2)+eps), one warp per token ----------------
__global__ void __launch_bounds__(256) k_rmsfac(const float* __restrict__ x) {
    int warp = threadIdx.x >> 5, lane = threadIdx.x & 31;
    int t = blockIdx.x * 8 + warp;
    const float4* xv = (const float4*)(x + (size_t)t * DM);
    float4 a = xv[lane], b = xv[lane + 32];
    float sq = a.x*a.x + a.y*a.y + a.z*a.z + a.w*a.w
             + b.x*b.x + b.y*b.y + b.z*b.z + b.w*b.w;
#pragma unroll
    for (int o = 16; o > 0; o >>= 1) sq += __shfl_xor_sync(0xffffffffu, sq, o);
    if (lane == 0) g_rfac[t] = rsqrtf(sq * (1.f / DM) + EPS);
}

// ---------------- qkv GEMM: BM=128, BN=64 (one head-part per tile), fused rms+rope ----
__global__ void __launch_bounds__(256) k_gemm_qkv_rope(const float* __restrict__ X,
                                                       const float* __restrict__ B,
                                                       const float* __restrict__ pos) {
    constexpr int BK = 16;
    constexpr int K = DM;
    __shared__ float As[2][BK][128];
    __shared__ float Bs[2][BK][64];
    extern __shared__ float Cs[];            // [128][68]

    int tid = threadIdx.x;
    int m0 = blockIdx.y * 128, n0 = blockIdx.x * 64;

    int arow = tid >> 1, akh = (tid & 1) * 8;
    int tokA = m0 + arow;
    int bA = tokA / (HH * WW);
    const float* Ag = X + (size_t)tokA * K + akh;
    const float* Sg = g_scale + bA * DM + akh;
    float rfac = g_rfac[tokA];
    int brow = tid >> 2, bkh = (tid & 3) * 4;
    const float* Bg = B + (size_t)(n0 + brow) * K + bkh;

    float ra[8], rb[4];
    {
        float4 v0 = *(const float4*)(Ag + 0);
        float4 v1 = *(const float4*)(Ag + 4);
        float4 s0 = *(const float4*)(Sg + 0);
        float4 s1 = *(const float4*)(Sg + 4);
        ra[0]=v0.x*s0.x*rfac; ra[1]=v0.y*s0.y*rfac; ra[2]=v0.z*s0.z*rfac; ra[3]=v0.w*s0.w*rfac;
        ra[4]=v1.x*s1.x*rfac; ra[5]=v1.y*s1.y*rfac; ra[6]=v1.z*s1.z*rfac; ra[7]=v1.w*s1.w*rfac;
        float4 w0 = *(const float4*)(Bg + 0);
        rb[0]=w0.x; rb[1]=w0.y; rb[2]=w0.z; rb[3]=w0.w;
    }
#pragma unroll
    for (int c = 0; c < 8; c++) As[0][akh + c][arow] = ra[c];
#pragma unroll
    for (int c = 0; c < 4; c++) Bs[0][bkh + c][brow] = rb[c];
    __syncthreads();

    int tx = tid & 15, ty = tid >> 4;
    unsigned long long acc[8][2];
#pragma unroll
    for (int i = 0; i < 8; i++) { acc[i][0] = 0ull; acc[i][1] = 0ull; }

    int nkt = K / BK;
    int buf = 0;
    for (int t = 0; t < nkt; t++) {
        if (t + 1 < nkt) {
            int k0 = (t + 1) * BK;
            float4 v0 = *(const float4*)(Ag + k0);
            float4 v1 = *(const float4*)(Ag + k0 + 4);
            float4 s0 = *(const float4*)(Sg + k0);
            float4 s1 = *(const float4*)(Sg + k0 + 4);
            ra[0]=v0.x*s0.x*rfac; ra[1]=v0.y*s0.y*rfac; ra[2]=v0.z*s0.z*rfac; ra[3]=v0.w*s0.w*rfac;
            ra[4]=v1.x*s1.x*rfac; ra[5]=v1.y*s1.y*rfac; ra[6]=v1.z*s1.z*rfac; ra[7]=v1.w*s1.w*rfac;
            float4 w0 = *(const float4*)(Bg + k0);
            rb[0]=w0.x; rb[1]=w0.y; rb[2]=w0.z; rb[3]=w0.w;
        }
#pragma unroll
        for (int kk = 0; kk < BK; kk++) {
            float4 a0 = *(const float4*)&As[buf][kk][ty * 8];
            float4 a1 = *(const float4*)&As[buf][kk][ty * 8 + 4];
            ulonglong2 b0 = *(const ulonglong2*)&Bs[buf][kk][tx * 4];
            unsigned long long ad[8];
            ad[0]=dupf(a0.x); ad[1]=dupf(a0.y); ad[2]=dupf(a0.z); ad[3]=dupf(a0.w);
            ad[4]=dupf(a1.x); ad[5]=dupf(a1.y); ad[6]=dupf(a1.z); ad[7]=dupf(a1.w);
#pragma unroll
            for (int i = 0; i < 8; i++) {
                ffma2(acc[i][0], ad[i], b0.x);
                ffma2(acc[i][1], ad[i], b0.y);
            }
        }
        if (t + 1 < nkt) {
            int nb = buf ^ 1;
#pragma unroll
            for (int c = 0; c < 8; c++) As[nb][akh + c][arow] = ra[c];
#pragma unroll
            for (int c = 0; c < 4; c++) Bs[nb][bkh + c][brow] = rb[c];
            __syncthreads();
            buf = nb;
        }
    }

    // stage 128x64 C tile in smem
#pragma unroll
    for (int i = 0; i < 8; i++) {
        int r = ty * 8 + i;
        float2 p0 = unpk(acc[i][0]), p1 = unpk(acc[i][1]);
        *(float4*)&Cs[r * 68 + tx * 4] = make_float4(p0.x, p0.y, p1.x, p1.y);
    }
    __syncthreads();

    // rope + permute readout: tile = one (part, head); thread -> (row, 32-col half)
    {
        int r = tid >> 1, half = tid & 1;
        int token = m0 + r;
        int b = token / (HH * WW);
        int ij = token - b * (HH * WW);
        int i = ij / WW, j = ij - i * WW;
        int part = n0 >> 8;              // 0=q 1=k 2=v
        int h = (n0 >> 6) & 3;
        float* dst = (part == 0 ? g_q : part == 1 ? g_k : g_v)
                   + ((size_t)((b * NHEAD + h) * HH + i) * WW + j) * EH + half * 32;
        const float* src = Cs + r * 68 + half * 32;

        if (part == 2) {
#pragma unroll
            for (int e4 = 0; e4 < 8; e4++)
                *(float4*)(dst + e4 * 4) = *(const float4*)(src + e4 * 4);
        } else {
            float sc = (part == 0) ? 0.125f : 1.f;
            if (half == 0) {             // cols 0..31: rotary pairs (e, e+16)
                float gh = pos[(i * WW + j) * 2 + 0];
                float gw = pos[(i * WW + j) * 2 + 1];
                float ov[32];
#pragma unroll
                for (int e = 0; e < 16; e++) {
                    float f  = 3.14159265358979323846f * exp10f((float)(e & 7) * 0.125f);
                    float p  = (e < 8) ? gh : gw;
                    float an = p * f;
                    float cs = cosf(an), sn = sinf(an);
                    float x1 = src[e], x2 = src[e + 16];
                    ov[e]      = x1 * cs - x2 * sn;
                    ov[e + 16] = x2 * cs + x1 * sn;
                }
#pragma unroll
                for (int e4 = 0; e4 < 8; e4++)
                    *(float4*)(dst + e4 * 4) = make_float4(ov[e4*4]*sc, ov[e4*4+1]*sc,
                                                           ov[e4*4+2]*sc, ov[e4*4+3]*sc);
            } else {                     // cols 32..63: passthrough * sc
#pragma unroll
                for (int e4 = 0; e4 < 8; e4++) {
                    float4 v = *(const float4*)(src + e4 * 4);
                    *(float4*)(dst + e4 * 4) = make_float4(v.x*sc, v.y*sc, v.z*sc, v.w*sc);
                }
            }
        }
    }
}

// ---------------- plain FFMA2 GEMM for output projection (BN=64) ----------------
__global__ void __launch_bounds__(256) k_gemm_out(const float* __restrict__ A,
                                                  const float* __restrict__ B,
                                                  const float* __restrict__ Sk,
                                                  float* __restrict__ C) {
    constexpr int BK = 16, K = DM, N = DM;
    __shared__ float As[2][BK][128];
    __shared__ float Bs[2][BK][64];

    int tid = threadIdx.x;
    int m0 = blockIdx.y * 128, n0 = blockIdx.x * 64;

    int arow = tid >> 1, akh = (tid & 1) * 8;
    int brow = tid >> 2, bkh = (tid & 3) * 4;
    const float* Ag = A + (size_t)(m0 + arow) * K + akh;
    const float* Bg = B + (size_t)(n0 + brow) * K + bkh;

    float ra[8], rb[4];
    {
        float4 v0 = *(const float4*)(Ag + 0);
        float4 v1 = *(const float4*)(Ag + 4);
        ra[0]=v0.x; ra[1]=v0.y; ra[2]=v0.z; ra[3]=v0.w;
        ra[4]=v1.x; ra[5]=v1.y; ra[6]=v1.z; ra[7]=v1.w;
        float4 w0 = *(const float4*)(Bg + 0);
        rb[0]=w0.x; rb[1]=w0.y; rb[2]=w0.z; rb[3]=w0.w;
    }
#pragma unroll
    for (int c = 0; c < 8; c++) As[0][akh + c][arow] = ra[c];
#pragma unroll
    for (int c = 0; c < 4; c++) Bs[0][bkh + c][brow] = rb[c];
    __syncthreads();

    int tx = tid & 15, ty = tid >> 4;
    unsigned long long acc[8][2];
#pragma unroll
    for (int i = 0; i < 8; i++) { acc[i][0] = 0ull; acc[i][1] = 0ull; }

    int nkt = K / BK;
    int buf = 0;
    for (int t = 0; t < nkt; t++) {
        if (t + 1 < nkt) {
            int k0 = (t + 1) * BK;
            float4 v0 = *(const float4*)(Ag + k0);
            float4 v1 = *(const float4*)(Ag + k0 + 4);
            ra[0]=v0.x; ra[1]=v0.y; ra[2]=v0.z; ra[3]=v0.w;
            ra[4]=v1.x; ra[5]=v1.y; ra[6]=v1.z; ra[7]=v1.w;
            float4 w0 = *(const float4*)(Bg + k0);
            rb[0]=w0.x; rb[1]=w0.y; rb[2]=w0.z; rb[3]=w0.w;
        }
#pragma unroll
        for (int kk = 0; kk < BK; kk++) {
            float4 a0 = *(const float4*)&As[buf][kk][ty * 8];
            float4 a1 = *(const float4*)&As[buf][kk][ty * 8 + 4];
            ulonglong2 b0 = *(const ulonglong2*)&Bs[buf][kk][tx * 4];
            unsigned long long ad[8];
            ad[0]=dupf(a0.x); ad[1]=dupf(a0.y); ad[2]=dupf(a0.z); ad[3]=dupf(a0.w);
            ad[4]=dupf(a1.x); ad[5]=dupf(a1.y); ad[6]=dupf(a1.z); ad[7]=dupf(a1.w);
#pragma unroll
            for (int i = 0; i < 8; i++) {
                ffma2(acc[i][0], ad[i], b0.x);
                ffma2(acc[i][1], ad[i], b0.y);
            }
        }
        if (t + 1 < nkt) {
            int nb = buf ^ 1;
#pragma unroll
            for (int c = 0; c < 8; c++) As[nb][akh + c][arow] = ra[c];
#pragma unroll
            for (int c = 0; c < 4; c++) Bs[nb][bkh + c][brow] = rb[c];
            __syncthreads();
            buf = nb;
        }
    }

#pragma unroll
    for (int i = 0; i < 8; i++) {
        int m = m0 + ty * 8 + i, nn = n0 + tx * 4;
        float2 p0 = unpk(acc[i][0]), p1 = unpk(acc[i][1]);
        float4 s = *(const float4*)&Sk[(size_t)m * N + nn];
        *(float4*)&C[(size_t)m * N + nn] =
            make_float4(p0.x + s.x, p0.y + s.y, p1.x + s.z, p1.y + s.w);
    }
}

// ---------------- attention v4: query-pair union sharing ----------------
// Warp = 2 adjacent-column queries. Lane owns a 7x8 union position: one K row
// load feeds both QK dots; one V row load feeds both AV accumulations.
#define KSS  68            // 272B rows: 16B-aligned, conflict-free LDS.128 phases
#define HALO 112           // 8 rows x 14 cols
__global__ void __launch_bounds__(256) k_attn() {
    extern __shared__ float sm[];
    float* ks = sm;                        // [112][68]
    float* qs = sm + HALO * KSS;           // [16][64]
    float* ps = qs + 16 * 64;              // [8 pairs][64 u][2]

    int j0 = blockIdx.x * 8;
    int i0 = blockIdx.y * 2;
    int bh = blockIdx.z;
    int b = bh >> 2, h = bh & 3;
    int tid = threadIdx.x;
    int warp = tid >> 5, lane = tid & 31;

    int r0 = min(max(i0 - 3, 0), HH - 8);
    int c0 = min(max(j0 - 3, 0), WW - 14);

    const float* kg = g_k + (size_t)(b * NHEAD + h) * HH * WW * EH;
    const float* vg = g_v + (size_t)(b * NHEAD + h) * HH * WW * EH;
    const float* qg = g_q + (size_t)(b * NHEAD + h) * HH * WW * EH;

    for (int idx = tid; idx < HALO * 16; idx += 256) {
        int p = idx >> 4, c4 = idx & 15;
        int r = r0 + p / 14, c = c0 + p % 14;
        *(float4*)(ks + p * KSS + c4 * 4) =
            *(const float4*)(kg + ((size_t)r * WW + c) * EH + c4 * 4);
    }
    for (int idx = tid; idx < 16 * 16; idx += 256) {
        int qi = idx >> 4, c4 = idx & 15;
        int iq = i0 + (qi >> 3), jq = j0 + (qi & 7);
        *(float4*)(qs + qi * 64 + c4 * 4) =
            *(const float4*)(qg + ((size_t)iq * WW + jq) * EH + c4 * 4);
    }
    __syncthreads();

    // pair for this warp: q0=(di, djp), q1=(di, djp+1)
    int di = warp >> 2, djp = (warp & 3) * 2;
    int iq = i0 + di, jq0 = j0 + djp;
    int sh  = min(max(iq - 3, 0), HH - 7);
    int sw0 = min(max(jq0 - 3, 0), WW - 7);
    int sw1 = min(max(jq0 - 2, 0), WW - 7);
    int dsw = sw1 - sw0;                   // 0 or 1
    int offq = (sh - r0) * 14 + (sw0 - c0);

    const float* q0row = qs + (di * 8 + djp) * 64;
    const float* q1row = q0row + 64;

    // union positions: uA = lane (0..31), uB = lane+32 (32..55, clamp dup)
    int uA = lane;
    int uB = min(lane + 32, 55);
    int cuA = uA & 7, cuB = uB & 7;
    const float* kA = ks + (offq + (uA >> 3) * 14 + cuA) * KSS;
    const float* kB = ks + (offq + (uB >> 3) * 14 + cuB) * KSS;

    unsigned long long s0A = 0ull, s1A = 0ull, s0B = 0ull, s1B = 0ull;
#pragma unroll
    for (int e = 0; e < 64; e += 4) {
        ulonglong2 qp0 = *(const ulonglong2*)(q0row + e);
        ulonglong2 qp1 = *(const ulonglong2*)(q1row + e);
        ulonglong2 ka  = *(const ulonglong2*)(kA + e);
        ulonglong2 kb  = *(const ulonglong2*)(kB + e);
        ffma2(s0A, qp0.x, ka.x); ffma2(s0A, qp0.y, ka.y);
        ffma2(s1A, qp1.x, ka.x); ffma2(s1A, qp1.y, ka.y);
        ffma2(s0B, qp0.x, kb.x); ffma2(s0B, qp0.y, kb.y);
        ffma2(s1B, qp1.x, kb.x); ffma2(s1B, qp1.y, kb.y);
    }
    // validity masks: q0 valid iff cu<7; q1 valid iff (dsw? cu>=1 : cu<7)
    bool okB   = (lane < 24);
    bool v0A   = (cuA < 7);
    bool v1A   = dsw ? (cuA >= 1) : (cuA < 7);
    bool v0B   = okB && (cuB < 7);
    bool v1B   = okB && (dsw ? (cuB >= 1) : (cuB < 7));

    float2 u0A = unpk(s0A), u1A = unpk(s1A), u0B = unpk(s0B), u1B = unpk(s1B);
    float sc0A = v0A ? (u0A.x + u0A.y) : -1e30f;
    float sc1A = v1A ? (u1A.x + u1A.y) : -1e30f;
    float sc0B = v0B ? (u0B.x + u0B.y) : -1e30f;
    float sc1B = v1B ? (u1B.x + u1B.y) : -1e30f;

    float mx0 = fmaxf(sc0A, sc0B), mx1 = fmaxf(sc1A, sc1B);
#pragma unroll
    for (int o = 16; o > 0; o >>= 1) {
        mx0 = fmaxf(mx0, __shfl_xor_sync(0xffffffffu, mx0, o));
        mx1 = fmaxf(mx1, __shfl_xor_sync(0xffffffffu, mx1, o));
    }
    float e0A = v0A ? __expf(sc0A - mx0) : 0.f;
    float e1A = v1A ? __expf(sc1A - mx1) : 0.f;
    float e0B = v0B ? __expf(sc0B - mx0) : 0.f;
    float e1B = v1B ? __expf(sc1B - mx1) : 0.f;
    float su0 = e0A + e0B, su1 = e1A + e1B;
#pragma unroll
    for (int o = 16; o > 0; o >>= 1) {
        su0 += __shfl_xor_sync(0xffffffffu, su0, o);
        su1 += __shfl_xor_sync(0xffffffffu, su1, o);
    }
    float inv0 = 1.f / su0, inv1 = 1.f / su1;

    float* pp = ps + warp * 128;           // [u][2] interleaved
    pp[2 * uA + 0] = e0A * inv0;
    pp[2 * uA + 1] = e1A * inv1;
    if (lane < 24) {
        pp[2 * uB + 0] = e0B * inv0;
        pp[2 * uB + 1] = e1B * inv1;
    }
    __syncwarp();

    // AV over union: one V row serves both queries
    unsigned long long acc0 = 0ull, acc1 = 0ull;
    const float* vA = vg + ((size_t)sh * WW + sw0) * EH + 2 * lane;
    const float* v7 = vg + ((size_t)sh * WW + sw1 + 6) * EH + 2 * lane;  // col for cu==7
#pragma unroll
    for (int u = 0; u < 56; u++) {
        int ru = u >> 3, cu = u & 7;
        float2 pv = *(const float2*)(pp + 2 * u);
        const float* vp = (cu < 7) ? (vA + (ru * WW + cu) * EH) : (v7 + ru * WW * EH);
        unsigned long long v = *(const unsigned long long*)vp;
        ffma2(acc0, dupf(pv.x), v);
        ffma2(acc1, dupf(pv.y), v);
    }
    float2 r0v = unpk(acc0), r1v = unpk(acc1);
    int tok0 = b * (HH * WW) + iq * WW + jq0;
    *(float2*)(g_o + (size_t)tok0 * DM + h * EH + 2 * lane) = r0v;
    *(float2*)(g_o + (size_t)(tok0 + 1) * DM + h * EH + 2 * lane) = r1v;
}

// ---------------- launch ----------------
extern "C" void kernel_launch(void* const* d_in, const int* in_sizes, int n_in,
                              void* d_out, int out_size) {
    const float* x      = (const float*)d_in[0];
    const float* pos    = (const float*)d_in[1];
    const float* cond   = (const float*)d_in[2];
    const float* w_norm = (const float*)d_in[3];
    const float* w_qkv  = (const float*)d_in[4];
    const float* w_out  = (const float*)d_in[5];
    float* out = (float*)d_out;

    k_scale<<<NB, 256>>>(cond, w_norm);
    k_rmsfac<<<TOK / 8, 256>>>(x);

    {
        size_t cs_bytes = 128 * 68 * sizeof(float);    // 34816
        cudaFuncSetAttribute(k_gemm_qkv_rope,
                             cudaFuncAttributeMaxDynamicSharedMemorySize, (int)cs_bytes);
        dim3 g1((3 * DM) / 64, TOK / 128);             // (12, 36) = 432 blocks
        k_gemm_qkv_rope<<<g1, 256, cs_bytes>>>(x, w_qkv, pos);
    }

    {
        size_t sm_bytes = (HALO * KSS + 16 * 64 + 8 * 128) * sizeof(float); // 38656
        cudaFuncSetAttribute(k_attn,
                             cudaFuncAttributeMaxDynamicSharedMemorySize, (int)sm_bytes);
        dim3 g2(WW / 8, HH / 2, NB * NHEAD);
        k_attn<<<g2, 256, sm_bytes>>>();
    }

    {
        float* go; cudaGetSymbolAddress((void**)&go, g_o);
        dim3 g3(DM / 64, TOK / 128);
        k_gemm_out<<<g3, 256>>>(go, w_out, x, out);
    }
}

// round 14
// speedup vs baseline: 1.3551x; 1.3551x over previous
#include <cuda_runtime.h>

#define TOK   4608      // n*H*W
#define NB    2
#define HH    48
#define WW    48
#define DM    256
#define NHEAD 4
#define EH    64
#define EPS   1e-6f

// ---------------- scratch ----------------
__device__ float g_scale[NB * DM];
__device__ float g_rfac [TOK];
__device__ float g_q   [NB * NHEAD * HH * WW * EH];
__device__ float g_k   [NB * NHEAD * HH * WW * EH];
__device__ float g_v   [NB * NHEAD * HH * WW * EH];
__device__ float g_o   [TOK * DM];

// ---------------- packed f32x2 helpers ----------------
__device__ __forceinline__ unsigned long long dupf(float x) {
    unsigned long long r;
    asm("mov.b64 %0,{%1,%2};" : "=l"(r) : "f"(x), "f"(x));
    return r;
}
__device__ __forceinline__ void ffma2(unsigned long long& c, unsigned long long a, unsigned long long b) {
    asm("fma.rn.f32x2 %0,%1,%2,%0;" : "+l"(c) : "l"(a), "l"(b));
}
__device__ __forceinline__ float2 unpk(unsigned long long v) {
    float2 r;
    asm("mov.b64 {%0,%1},%2;" : "=f"(r.x), "=f"(r.y) : "l"(v));
    return r;
}

// ---------------- K0: scale[b][c] = dot(cond[b], w_norm[c]) + 1 ----------------
__global__ void k_scale(const float* __restrict__ cond, const float* __restrict__ w_norm) {
    int b = blockIdx.x, c = threadIdx.x;
    const float4* cv = (const float4*)(cond + b * DM);
    const float4* wv = (const float4*)(w_norm + c * DM);
    float s = 0.f;
#pragma unroll 16
    for (int k = 0; k < DM / 4; k++) {
        float4 a = cv[k], w = wv[k];
        s += a.x * w.x + a.y * w.y + a.z * w.z + a.w * w.w;
    }
    g_scale[b * DM + c] = s + 1.f;
}

// ---------------- K1: per-token rsqrt(mean(x^2)+eps), one warp per token ----------------
__global__ void __launch_bounds__(256) k_rmsfac(const float* __restrict__ x) {
    int warp = threadIdx.x >> 5, lane = threadIdx.x & 31;
    int t = blockIdx.x * 8 + warp;
    const float4* xv = (const float4*)(x + (size_t)t * DM);
    float4 a = xv[lane], b = xv[lane + 32];
    float sq = a.x*a.x + a.y*a.y + a.z*a.z + a.w*a.w
             + b.x*b.x + b.y*b.y + b.z*b.z + b.w*b.w;
#pragma unroll
    for (int o = 16; o > 0; o >>= 1) sq += __shfl_xor_sync(0xffffffffu, sq, o);
    if (lane == 0) g_rfac[t] = rsqrtf(sq * (1.f / DM) + EPS);
}

// ---------------- qkv GEMM (BM=128,BN=128, fused rms-norm A-load) + rope epilogue ----
__global__ void __launch_bounds__(256) k_gemm_qkv_rope(const float* __restrict__ X,
                                                       const float* __restrict__ B,
                                                       const float* __restrict__ pos) {
    constexpr int BM = 128, BK = 16, BN = 128;
    constexpr int K = DM;
    __shared__ float As[2][BK][BM];
    __shared__ float Bs[2][BK][BN];
    extern __shared__ float Cs[];            // [128][132]

    int tid = threadIdx.x;
    int m0 = blockIdx.y * BM, n0 = blockIdx.x * BN;

    int arow = tid >> 1, akh = (tid & 1) * 8;
    int tokA = m0 + arow;
    int bA = tokA / (HH * WW);
    const float* Ag = X + (size_t)tokA * K + akh;
    const float* Sg = g_scale + bA * DM + akh;
    float rfac = g_rfac[tokA];
    const float* Bg = B + (size_t)(n0 + arow) * K + akh;

    float ra[8], rb[8];
    {
        float4 v0 = *(const float4*)(Ag + 0);
        float4 v1 = *(const float4*)(Ag + 4);
        float4 s0 = *(const float4*)(Sg + 0);
        float4 s1 = *(const float4*)(Sg + 4);
        ra[0]=v0.x*s0.x*rfac; ra[1]=v0.y*s0.y*rfac; ra[2]=v0.z*s0.z*rfac; ra[3]=v0.w*s0.w*rfac;
        ra[4]=v1.x*s1.x*rfac; ra[5]=v1.y*s1.y*rfac; ra[6]=v1.z*s1.z*rfac; ra[7]=v1.w*s1.w*rfac;
        float4 w0 = *(const float4*)(Bg + 0);
        float4 w1 = *(const float4*)(Bg + 4);
        rb[0]=w0.x; rb[1]=w0.y; rb[2]=w0.z; rb[3]=w0.w;
        rb[4]=w1.x; rb[5]=w1.y; rb[6]=w1.z; rb[7]=w1.w;
    }
#pragma unroll
    for (int c = 0; c < 8; c++) { As[0][akh + c][arow] = ra[c]; Bs[0][akh + c][arow] = rb[c]; }
    __syncthreads();

    int tx = tid & 15, ty = tid >> 4;
    unsigned long long acc[8][4];
#pragma unroll
    for (int i = 0; i < 8; i++)
#pragma unroll
        for (int j = 0; j < 4; j++) acc[i][j] = 0ull;

    int nkt = K / BK;
    int buf = 0;
    for (int t = 0; t < nkt; t++) {
        if (t + 1 < nkt) {
            int k0 = (t + 1) * BK;
            float4 v0 = *(const float4*)(Ag + k0);
            float4 v1 = *(const float4*)(Ag + k0 + 4);
            float4 s0 = *(const float4*)(Sg + k0);
            float4 s1 = *(const float4*)(Sg + k0 + 4);
            ra[0]=v0.x*s0.x*rfac; ra[1]=v0.y*s0.y*rfac; ra[2]=v0.z*s0.z*rfac; ra[3]=v0.w*s0.w*rfac;
            ra[4]=v1.x*s1.x*rfac; ra[5]=v1.y*s1.y*rfac; ra[6]=v1.z*s1.z*rfac; ra[7]=v1.w*s1.w*rfac;
            float4 w0 = *(const float4*)(Bg + k0);
            float4 w1 = *(const float4*)(Bg + k0 + 4);
            rb[0]=w0.x; rb[1]=w0.y; rb[2]=w0.z; rb[3]=w0.w;
            rb[4]=w1.x; rb[5]=w1.y; rb[6]=w1.z; rb[7]=w1.w;
        }
#pragma unroll
        for (int kk = 0; kk < BK; kk++) {
            float4 a0 = *(const float4*)&As[buf][kk][ty * 8];
            float4 a1 = *(const float4*)&As[buf][kk][ty * 8 + 4];
            ulonglong2 b0 = *(const ulonglong2*)&Bs[buf][kk][tx * 4];
            ulonglong2 b1 = *(const ulonglong2*)&Bs[buf][kk][64 + tx * 4];
            unsigned long long ad[8];
            ad[0]=dupf(a0.x); ad[1]=dupf(a0.y); ad[2]=dupf(a0.z); ad[3]=dupf(a0.w);
            ad[4]=dupf(a1.x); ad[5]=dupf(a1.y); ad[6]=dupf(a1.z); ad[7]=dupf(a1.w);
#pragma unroll
            for (int i = 0; i < 8; i++) {
                ffma2(acc[i][0], ad[i], b0.x);
                ffma2(acc[i][1], ad[i], b0.y);
                ffma2(acc[i][2], ad[i], b1.x);
                ffma2(acc[i][3], ad[i], b1.y);
            }
        }
        if (t + 1 < nkt) {
            int nb = buf ^ 1;
#pragma unroll
            for (int c = 0; c < 8; c++) { As[nb][akh + c][arow] = ra[c]; Bs[nb][akh + c][arow] = rb[c]; }
            __syncthreads();
            buf = nb;
        }
    }

#pragma unroll
    for (int i = 0; i < 8; i++) {
        int r = ty * 8 + i;
        float2 p0 = unpk(acc[i][0]), p1 = unpk(acc[i][1]);
        float2 p2 = unpk(acc[i][2]), p3 = unpk(acc[i][3]);
        *(float4*)&Cs[r * 132 + tx * 4]      = make_float4(p0.x, p0.y, p1.x, p1.y);
        *(float4*)&Cs[r * 132 + 64 + tx * 4] = make_float4(p2.x, p2.y, p3.x, p3.y);
    }
    __syncthreads();

    {
        int r = tid >> 1, half = tid & 1;
        int token = m0 + r;
        int b = token / (HH * WW);
        int ij = token - b * (HH * WW);
        int i = ij / WW, j = ij - i * WW;
        int c_lo = n0 + half * 64;
        int part = c_lo >> 8;            // 0=q 1=k 2=v
        int rem  = c_lo & 255;
        int h = rem >> 6;
        float* dst = (part == 0 ? g_q : part == 1 ? g_k : g_v)
                   + ((size_t)((b * NHEAD + h) * HH + i) * WW + j) * EH;
        const float* src = Cs + r * 132 + half * 64;

        if (part == 2) {
#pragma unroll
            for (int e4 = 0; e4 < 16; e4++)
                *(float4*)(dst + e4 * 4) = *(const float4*)(src + e4 * 4);
        } else {
            float gh = pos[(i * WW + j) * 2 + 0];
            float gw = pos[(i * WW + j) * 2 + 1];
            float ov[32];
#pragma unroll
            for (int e = 0; e < 16; e++) {
                float f  = 3.14159265358979323846f * exp10f((float)(e & 7) * 0.125f);
                float p  = (e < 8) ? gh : gw;
                float an = p * f;
                float cs = cosf(an), sn = sinf(an);
                float x1 = src[e], x2 = src[e + 16];
                ov[e]      = x1 * cs - x2 * sn;
                ov[e + 16] = x2 * cs + x1 * sn;
            }
            float sc = (part == 0) ? 0.125f : 1.f;
#pragma unroll
            for (int e4 = 0; e4 < 8; e4++)
                *(float4*)(dst + e4 * 4) = make_float4(ov[e4*4]*sc, ov[e4*4+1]*sc,
                                                       ov[e4*4+2]*sc, ov[e4*4+3]*sc);
#pragma unroll
            for (int e4 = 8; e4 < 16; e4++) {
                float4 v = *(const float4*)(src + e4 * 4);
                *(float4*)(dst + e4 * 4) = make_float4(v.x*sc, v.y*sc, v.z*sc, v.w*sc);
            }
        }
    }
}

// ---------------- plain FFMA2 GEMM for output projection (BN=64) ----------------
__global__ void __launch_bounds__(256) k_gemm_out(const float* __restrict__ A,
                                                  const float* __restrict__ B,
                                                  const float* __restrict__ Sk,
                                                  float* __restrict__ C) {
    constexpr int BK = 16, K = DM, N = DM;
    __shared__ float As[2][BK][128];
    __shared__ float Bs[2][BK][64];

    int tid = threadIdx.x;
    int m0 = blockIdx.y * 128, n0 = blockIdx.x * 64;

    int arow = tid >> 1, akh = (tid & 1) * 8;
    int brow = tid >> 2, bkh = (tid & 3) * 4;
    const float* Ag = A + (size_t)(m0 + arow) * K + akh;
    const float* Bg = B + (size_t)(n0 + brow) * K + bkh;

    float ra[8], rb[4];
    {
        float4 v0 = *(const float4*)(Ag + 0);
        float4 v1 = *(const float4*)(Ag + 4);
        ra[0]=v0.x; ra[1]=v0.y; ra[2]=v0.z; ra[3]=v0.w;
        ra[4]=v1.x; ra[5]=v1.y; ra[6]=v1.z; ra[7]=v1.w;
        float4 w0 = *(const float4*)(Bg + 0);
        rb[0]=w0.x; rb[1]=w0.y; rb[2]=w0.z; rb[3]=w0.w;
    }
#pragma unroll
    for (int c = 0; c < 8; c++) As[0][akh + c][arow] = ra[c];
#pragma unroll
    for (int c = 0; c < 4; c++) Bs[0][bkh + c][brow] = rb[c];
    __syncthreads();

    int tx = tid & 15, ty = tid >> 4;
    unsigned long long acc[8][2];
#pragma unroll
    for (int i = 0; i < 8; i++) { acc[i][0] = 0ull; acc[i][1] = 0ull; }

    int nkt = K / BK;
    int buf = 0;
    for (int t = 0; t < nkt; t++) {
        if (t + 1 < nkt) {
            int k0 = (t + 1) * BK;
            float4 v0 = *(const float4*)(Ag + k0);
            float4 v1 = *(const float4*)(Ag + k0 + 4);
            ra[0]=v0.x; ra[1]=v0.y; ra[2]=v0.z; ra[3]=v0.w;
            ra[4]=v1.x; ra[5]=v1.y; ra[6]=v1.z; ra[7]=v1.w;
            float4 w0 = *(const float4*)(Bg + k0);
            rb[0]=w0.x; rb[1]=w0.y; rb[2]=w0.z; rb[3]=w0.w;
        }
#pragma unroll
        for (int kk = 0; kk < BK; kk++) {
            float4 a0 = *(const float4*)&As[buf][kk][ty * 8];
            float4 a1 = *(const float4*)&As[buf][kk][ty * 8 + 4];
            ulonglong2 b0 = *(const ulonglong2*)&Bs[buf][kk][tx * 4];
            unsigned long long ad[8];
            ad[0]=dupf(a0.x); ad[1]=dupf(a0.y); ad[2]=dupf(a0.z); ad[3]=dupf(a0.w);
            ad[4]=dupf(a1.x); ad[5]=dupf(a1.y); ad[6]=dupf(a1.z); ad[7]=dupf(a1.w);
#pragma unroll
            for (int i = 0; i < 8; i++) {
                ffma2(acc[i][0], ad[i], b0.x);
                ffma2(acc[i][1], ad[i], b0.y);
            }
        }
        if (t + 1 < nkt) {
            int nb = buf ^ 1;
#pragma unroll
            for (int c = 0; c < 8; c++) As[nb][akh + c][arow] = ra[c];
#pragma unroll
            for (int c = 0; c < 4; c++) Bs[nb][bkh + c][brow] = rb[c];
            __syncthreads();
            buf = nb;
        }
    }

#pragma unroll
    for (int i = 0; i < 8; i++) {
        int m = m0 + ty * 8 + i, nn = n0 + tx * 4;
        float2 p0 = unpk(acc[i][0]), p1 = unpk(acc[i][1]);
        float4 s = *(const float4*)&Sk[(size_t)m * N + nn];
        *(float4*)&C[(size_t)m * N + nn] =
            make_float4(p0.x + s.x, p0.y + s.y, p1.x + s.z, p1.y + s.w);
    }
}

// ---------------- attention v5: K-halo-only smem (7 blocks/SM), q via LDG, probs via shfl
#define KSS  68            // 272B rows: 16B-aligned, conflict-free LDS.128 phases
#define HALO 112           // 8 rows x 14 cols
__global__ void __launch_bounds__(256) k_attn() {
    extern __shared__ float sm[];
    float* ks = sm;                        // [112][68] = 30464B, the ONLY smem

    int j0 = blockIdx.x * 8;
    int i0 = blockIdx.y * 2;
    int bh = blockIdx.z;
    int b = bh >> 2, h = bh & 3;
    int tid = threadIdx.x;
    int warp = tid >> 5, lane = tid & 31;

    int r0 = min(max(i0 - 3, 0), HH - 8);
    int c0 = min(max(j0 - 3, 0), WW - 14);

    const float* kg = g_k + (size_t)(b * NHEAD + h) * HH * WW * EH;
    const float* vg = g_v + (size_t)(b * NHEAD + h) * HH * WW * EH;
    const float* qg = g_q + (size_t)(b * NHEAD + h) * HH * WW * EH;

    // K halo fill: float4 both sides
    for (int idx = tid; idx < HALO * 16; idx += 256) {
        int p = idx >> 4, c4 = idx & 15;
        int r = r0 + p / 14, c = c0 + p % 14;
        *(float4*)(ks + p * KSS + c4 * 4) =
            *(const float4*)(kg + ((size_t)r * WW + c) * EH + c4 * 4);
    }
    __syncthreads();

#pragma unroll
    for (int s = 0; s < 2; s++) {
        int qi = warp * 2 + s;
        int di = qi >> 3, dj = qi & 7;
        int iq = i0 + di, jq = j0 + dj;
        int sh = min(max(iq - 3, 0), HH - 7);
        int sw = min(max(jq - 3, 0), WW - 7);
        int offq = (sh - r0) * 14 + (sw - c0);

        // QK: lane owns positions pA=lane, pB=lane+32 (clamped; lanes>=17 discarded)
        int pA = lane;
        int pB = min(lane + 32, 48);
        const float* kA = ks + (offq + (pA / 7) * 14 + pA % 7) * KSS;
        const float* kB = ks + (offq + (pB / 7) * 14 + pB % 7) * KSS;
        const float* qrow = qg + ((size_t)iq * WW + jq) * EH;   // uniform gmem, L1-hot
        unsigned long long a0 = 0ull, a1 = 0ull, b0 = 0ull, b1 = 0ull;
#pragma unroll
        for (int e = 0; e < 64; e += 4) {
            ulonglong2 qp = *(const ulonglong2*)(qrow + e);
            ulonglong2 ka = *(const ulonglong2*)(kA + e);
            ulonglong2 kb = *(const ulonglong2*)(kB + e);
            ffma2(a0, qp.x, ka.x); ffma2(a1, qp.y, ka.y);
            ffma2(b0, qp.x, kb.x); ffma2(b1, qp.y, kb.y);
        }
        float2 uA0 = unpk(a0), uA1 = unpk(a1);
        float2 uB0 = unpk(b0), uB1 = unpk(b1);
        float sA = (uA0.x + uA0.y) + (uA1.x + uA1.y);
        float sB = (lane < 17) ? (uB0.x + uB0.y) + (uB1.x + uB1.y) : -1e30f;

        float mx = fmaxf(sA, sB);
#pragma unroll
        for (int o = 16; o > 0; o >>= 1) mx = fmaxf(mx, __shfl_xor_sync(0xffffffffu, mx, o));
        float eA = __expf(sA - mx);
        float eB = (lane < 17) ? __expf(sB - mx) : 0.f;
        float sum = eA + eB;
#pragma unroll
        for (int o = 16; o > 0; o >>= 1) sum += __shfl_xor_sync(0xffffffffu, sum, o);
        float inv = 1.f / sum;
        float w0 = eA * inv;          // prob for position lane
        float w1 = eB * inv;          // prob for position 32+lane (lanes 0..16)

        // AV: V from gmem with compile-time offsets; probs broadcast via shfl
        unsigned long long acc = 0ull;
        const float* vbase = vg + ((size_t)sh * WW + sw) * EH + 2 * lane;
#pragma unroll
        for (int p = 0; p < 49; p++) {
            float a = (p < 32) ? __shfl_sync(0xffffffffu, w0, p)
                               : __shfl_sync(0xffffffffu, w1, p - 32);
            ffma2(acc, dupf(a),
                  *(const unsigned long long*)(vbase + ((p / 7) * WW + (p % 7)) * EH));
        }
        float2 r = unpk(acc);
        int tok = b * (HH * WW) + iq * WW + jq;
        *(float2*)(g_o + (size_t)tok * DM + h * EH + 2 * lane) = r;
    }
}

// ---------------- launch ----------------
extern "C" void kernel_launch(void* const* d_in, const int* in_sizes, int n_in,
                              void* d_out, int out_size) {
    const float* x      = (const float*)d_in[0];
    const float* pos    = (const float*)d_in[1];
    const float* cond   = (const float*)d_in[2];
    const float* w_norm = (const float*)d_in[3];
    const float* w_qkv  = (const float*)d_in[4];
    const float* w_out  = (const float*)d_in[5];
    float* out = (float*)d_out;

    k_scale<<<NB, 256>>>(cond, w_norm);
    k_rmsfac<<<TOK / 8, 256>>>(x);

    {
        size_t cs_bytes = 128 * 132 * sizeof(float);   // 67584
        cudaFuncSetAttribute(k_gemm_qkv_rope,
                             cudaFuncAttributeMaxDynamicSharedMemorySize, (int)cs_bytes);
        dim3 g1((3 * DM) / 128, TOK / 128);            // (6, 36) = 216 blocks
        k_gemm_qkv_rope<<<g1, 256, cs_bytes>>>(x, w_qkv, pos);
    }

    {
        size_t sm_bytes = HALO * KSS * sizeof(float);  // 30464 -> 7 blocks/SM
        cudaFuncSetAttribute(k_attn,
                             cudaFuncAttributeMaxDynamicSharedMemorySize, (int)sm_bytes);
        dim3 g2(WW / 8, HH / 2, NB * NHEAD);
        k_attn<<<g2, 256, sm_bytes>>>();
    }

    {
        float* go; cudaGetSymbolAddress((void**)&go, g_o);
        dim3 g3(DM / 64, TOK / 128);
        k_gemm_out<<<g3, 256>>>(go, w_out, x, out);
    }
}

// round 15
// speedup vs baseline: 1.4716x; 1.0860x over previous
#include <cuda_runtime.h>
#include <mma.h>
using namespace nvcuda;

#define TOK   4608      // n*H*W
#define NB    2
#define HH    48
#define WW    48
#define DM    256
#define NHEAD 4
#define EH    64
#define EPS   1e-6f

// ---------------- scratch ----------------
__device__ float g_scale[NB * DM];
__device__ float g_rfac [TOK];
__device__ float g_q   [NB * NHEAD * HH * WW * EH];
__device__ float g_k   [NB * NHEAD * HH * WW * EH];
__device__ float g_v   [NB * NHEAD * HH * WW * EH];
__device__ float g_o   [TOK * DM];

// ---------------- packed f32x2 helpers (attn) ----------------
__device__ __forceinline__ unsigned long long dupf(float x) {
    unsigned long long r;
    asm("mov.b64 %0,{%1,%2};" : "=l"(r) : "f"(x), "f"(x));
    return r;
}
__device__ __forceinline__ void ffma2(unsigned long long& c, unsigned long long a, unsigned long long b) {
    asm("fma.rn.f32x2 %0,%1,%2,%0;" : "+l"(c) : "l"(a), "l"(b));
}
__device__ __forceinline__ float2 unpk(unsigned long long v) {
    float2 r;
    asm("mov.b64 {%0,%1},%2;" : "=f"(r.x), "=f"(r.y) : "l"(v));
    return r;
}

// ---------------- K0: scale[b][c] = dot(cond[b], w_norm[c]) + 1 ----------------
__global__ void k_scale(const float* __restrict__ cond, const float* __restrict__ w_norm) {
    int b = blockIdx.x, c = threadIdx.x;
    const float4* cv = (const float4*)(cond + b * DM);
    const float4* wv = (const float4*)(w_norm + c * DM);
    float s = 0.f;
#pragma unroll 16
    for (int k = 0; k < DM / 4; k++) {
        float4 a = cv[k], w = wv[k];
        s += a.x * w.x + a.y * w.y + a.z * w.z + a.w * w.w;
    }
    g_scale[b * DM + c] = s + 1.f;
}

// ---------------- K1: per-token rsqrt(mean(x^2)+eps) ----------------
__global__ void __launch_bounds__(256) k_rmsfac(const float* __restrict__ x) {
    int warp = threadIdx.x >> 5, lane = threadIdx.x & 31;
    int t = blockIdx.x * 8 + warp;
    const float4* xv = (const float4*)(x + (size_t)t * DM);
    float4 a = xv[lane], b = xv[lane + 32];
    float sq = a.x*a.x + a.y*a.y + a.z*a.z + a.w*a.w
             + b.x*b.x + b.y*b.y + b.z*b.z + b.w*b.w;
#pragma unroll
    for (int o = 16; o > 0; o >>= 1) sq += __shfl_xor_sync(0xffffffffu, sq, o);
    if (lane == 0) g_rfac[t] = rsqrtf(sq * (1.f / DM) + EPS);
}

// ============ qkv GEMM via wmma tf32 (BM=128,BN=128,BK=32) + fused rms + rope ==========
// smem: mainloop uses As[128][36] | Bs[128][36]; epilogue reuses region as Cs[128][132]
__global__ void __launch_bounds__(256) k_gemm_qkv_rope(const float* __restrict__ X,
                                                       const float* __restrict__ W,
                                                       const float* __restrict__ pos) {
    constexpr int K = DM, LDT = 36, LDC = 132;
    extern __shared__ float smem[];
    float* As = smem;                 // [128][36]
    float* Bs = smem + 128 * LDT;     // [128][36]
    float* Cs = smem;                 // [128][132] (reused after mainloop)

    int tid = threadIdx.x;
    int m0 = blockIdx.y * 128, n0 = blockIdx.x * 128;
    int warp = tid >> 5;
    int wm = warp >> 2, wn = warp & 3;      // 2 x 4 warp grid; warp tile 64x32

    int row = tid >> 1, colh = (tid & 1) * 16;
    int tokA = m0 + row;
    int bA = tokA / (HH * WW);
    const float* Ag = X + (size_t)tokA * K;
    const float* Sg = g_scale + bA * DM;
    float rfac = g_rfac[tokA];
    const float* Bg = W + (size_t)(n0 + row) * K;

    wmma::fragment<wmma::accumulator, 16, 16, 8, float> cf[4][2];
#pragma unroll
    for (int i = 0; i < 4; i++)
#pragma unroll
        for (int j = 0; j < 2; j++) wmma::fill_fragment(cf[i][j], 0.f);

    for (int kt = 0; kt < K / 32; kt++) {
        int k0 = kt * 32;
        __syncthreads();
#pragma unroll
        for (int c4 = 0; c4 < 4; c4++) {
            float4 v = *(const float4*)(Ag + k0 + colh + c4 * 4);
            float4 s = *(const float4*)(Sg + k0 + colh + c4 * 4);
            *(float4*)(As + row * LDT + colh + c4 * 4) =
                make_float4(v.x*s.x*rfac, v.y*s.y*rfac, v.z*s.z*rfac, v.w*s.w*rfac);
            *(float4*)(Bs + row * LDT + colh + c4 * 4) =
                *(const float4*)(Bg + k0 + colh + c4 * 4);
        }
        __syncthreads();
#pragma unroll
        for (int ks = 0; ks < 4; ks++) {
            int kk = ks * 8;
            wmma::fragment<wmma::matrix_a, 16, 16, 8, wmma::precision::tf32, wmma::row_major> af[4];
            wmma::fragment<wmma::matrix_b, 16, 16, 8, wmma::precision::tf32, wmma::col_major> bf[2];
#pragma unroll
            for (int i = 0; i < 4; i++) {
                wmma::load_matrix_sync(af[i], As + (wm * 64 + i * 16) * LDT + kk, LDT);
#pragma unroll
                for (int t = 0; t < af[i].num_elements; t++)
                    af[i].x[t] = wmma::__float_to_tf32(af[i].x[t]);
            }
#pragma unroll
            for (int j = 0; j < 2; j++) {
                wmma::load_matrix_sync(bf[j], Bs + (wn * 32 + j * 16) * LDT + kk, LDT);
#pragma unroll
                for (int t = 0; t < bf[j].num_elements; t++)
                    bf[j].x[t] = wmma::__float_to_tf32(bf[j].x[t]);
            }
#pragma unroll
            for (int i = 0; i < 4; i++)
#pragma unroll
                for (int j = 0; j < 2; j++)
                    wmma::mma_sync(cf[i][j], af[i], bf[j], cf[i][j]);
        }
    }
    __syncthreads();           // mainloop smem reads done; safe to overwrite as Cs
#pragma unroll
    for (int i = 0; i < 4; i++)
#pragma unroll
        for (int j = 0; j < 2; j++)
            wmma::store_matrix_sync(Cs + (wm * 64 + i * 16) * LDC + wn * 32 + j * 16,
                                    cf[i][j], LDC, wmma::mem_row_major);
    __syncthreads();

    // rope + permute readout (as R10): thread -> (row, 64-col half)
    {
        int r = tid >> 1, half = tid & 1;
        int token = m0 + r;
        int b = token / (HH * WW);
        int ij = token - b * (HH * WW);
        int i = ij / WW, j = ij - i * WW;
        int c_lo = n0 + half * 64;
        int part = c_lo >> 8;            // 0=q 1=k 2=v
        int h = (c_lo & 255) >> 6;
        float* dst = (part == 0 ? g_q : part == 1 ? g_k : g_v)
                   + ((size_t)((b * NHEAD + h) * HH + i) * WW + j) * EH;
        const float* src = Cs + r * LDC + half * 64;

        if (part == 2) {
#pragma unroll
            for (int e4 = 0; e4 < 16; e4++)
                *(float4*)(dst + e4 * 4) = *(const float4*)(src + e4 * 4);
        } else {
            float gh = pos[(i * WW + j) * 2 + 0];
            float gw = pos[(i * WW + j) * 2 + 1];
            float ov[32];
#pragma unroll
            for (int e = 0; e < 16; e++) {
                float f  = 3.14159265358979323846f * exp10f((float)(e & 7) * 0.125f);
                float p  = (e < 8) ? gh : gw;
                float an = p * f;
                float cs = cosf(an), sn = sinf(an);
                float x1 = src[e], x2 = src[e + 16];
                ov[e]      = x1 * cs - x2 * sn;
                ov[e + 16] = x2 * cs + x1 * sn;
            }
            float sc = (part == 0) ? 0.125f : 1.f;
#pragma unroll
            for (int e4 = 0; e4 < 8; e4++)
                *(float4*)(dst + e4 * 4) = make_float4(ov[e4*4]*sc, ov[e4*4+1]*sc,
                                                       ov[e4*4+2]*sc, ov[e4*4+3]*sc);
#pragma unroll
            for (int e4 = 8; e4 < 16; e4++) {
                float4 v = *(const float4*)(src + e4 * 4);
                *(float4*)(dst + e4 * 4) = make_float4(v.x*sc, v.y*sc, v.z*sc, v.w*sc);
            }
        }
    }
}

// ============ out GEMM via wmma tf32 (BM=128,BN=64,BK=32) + skip ==========
__global__ void __launch_bounds__(256) k_gemm_out(const float* __restrict__ A,
                                                  const float* __restrict__ W,
                                                  const float* __restrict__ Sk,
                                                  float* __restrict__ C) {
    constexpr int K = DM, N = DM, LDT = 36, LDC = 68;
    extern __shared__ float smem[];
    float* As = smem;                 // [128][36]
    float* Bs = smem + 128 * LDT;     // [64][36]
    float* Cs = smem;                 // [128][68] (reused)

    int tid = threadIdx.x;
    int m0 = blockIdx.y * 128, n0 = blockIdx.x * 64;
    int warp = tid >> 5;
    int wm = warp >> 1, wn = warp & 1;      // 4 x 2 warp grid; warp tile 32x32

    int arow = tid >> 1, acolh = (tid & 1) * 16;
    const float* Ag = A + (size_t)(m0 + arow) * K;
    int brow = tid >> 2, bcolh = (tid & 3) * 8;
    const float* Bg = W + (size_t)(n0 + brow) * K;

    wmma::fragment<wmma::accumulator, 16, 16, 8, float> cf[2][2];
#pragma unroll
    for (int i = 0; i < 2; i++)
#pragma unroll
        for (int j = 0; j < 2; j++) wmma::fill_fragment(cf[i][j], 0.f);

    for (int kt = 0; kt < K / 32; kt++) {
        int k0 = kt * 32;
        __syncthreads();
#pragma unroll
        for (int c4 = 0; c4 < 4; c4++)
            *(float4*)(As + arow * LDT + acolh + c4 * 4) =
                *(const float4*)(Ag + k0 + acolh + c4 * 4);
#pragma unroll
        for (int c4 = 0; c4 < 2; c4++)
            *(float4*)(Bs + brow * LDT + bcolh + c4 * 4) =
                *(const float4*)(Bg + k0 + bcolh + c4 * 4);
        __syncthreads();
#pragma unroll
        for (int ks = 0; ks < 4; ks++) {
            int kk = ks * 8;
            wmma::fragment<wmma::matrix_a, 16, 16, 8, wmma::precision::tf32, wmma::row_major> af[2];
            wmma::fragment<wmma::matrix_b, 16, 16, 8, wmma::precision::tf32, wmma::col_major> bf[2];
#pragma unroll
            for (int i = 0; i < 2; i++) {
                wmma::load_matrix_sync(af[i], As + (wm * 32 + i * 16) * LDT + kk, LDT);
#pragma unroll
                for (int t = 0; t < af[i].num_elements; t++)
                    af[i].x[t] = wmma::__float_to_tf32(af[i].x[t]);
            }
#pragma unroll
            for (int j = 0; j < 2; j++) {
                wmma::load_matrix_sync(bf[j], Bs + (wn * 32 + j * 16) * LDT + kk, LDT);
#pragma unroll
                for (int t = 0; t < bf[j].num_elements; t++)
                    bf[j].x[t] = wmma::__float_to_tf32(bf[j].x[t]);
            }
#pragma unroll
            for (int i = 0; i < 2; i++)
#pragma unroll
                for (int j = 0; j < 2; j++)
                    wmma::mma_sync(cf[i][j], af[i], bf[j], cf[i][j]);
        }
    }
    __syncthreads();
#pragma unroll
    for (int i = 0; i < 2; i++)
#pragma unroll
        for (int j = 0; j < 2; j++)
            wmma::store_matrix_sync(Cs + (wm * 32 + i * 16) * LDC + wn * 32 + j * 16,
                                    cf[i][j], LDC, wmma::mem_row_major);
    __syncthreads();

    {
        int r = tid >> 1, half = tid & 1;
        int m = m0 + r, nn = n0 + half * 32;
        const float* src = Cs + r * LDC + half * 32;
#pragma unroll
        for (int c4 = 0; c4 < 8; c4++) {
            float4 v = *(const float4*)(src + c4 * 4);
            float4 s = *(const float4*)&Sk[(size_t)m * N + nn + c4 * 4];
            *(float4*)&C[(size_t)m * N + nn + c4 * 4] =
                make_float4(v.x + s.x, v.y + s.y, v.z + s.z, v.w + s.w);
        }
    }
}

// ---------------- attention v3 (verbatim R10, proven 33.8us) ----------------
#define KSS  68
#define ASS  52
#define HALO 112
__global__ void __launch_bounds__(256) k_attn() {
    extern __shared__ float sm[];
    float* ks  = sm;                       // [112][68]
    float* qs  = sm + HALO * KSS;          // [16][64]
    float* as_ = qs + 16 * 64;             // [16][52]

    int j0 = blockIdx.x * 8;
    int i0 = blockIdx.y * 2;
    int bh = blockIdx.z;
    int b = bh >> 2, h = bh & 3;
    int tid = threadIdx.x;
    int warp = tid >> 5, lane = tid & 31;

    int r0 = min(max(i0 - 3, 0), HH - 8);
    int c0 = min(max(j0 - 3, 0), WW - 14);

    const float* kg = g_k + (size_t)(b * NHEAD + h) * HH * WW * EH;
    const float* vg = g_v + (size_t)(b * NHEAD + h) * HH * WW * EH;
    const float* qg = g_q + (size_t)(b * NHEAD + h) * HH * WW * EH;

    for (int idx = tid; idx < HALO * 16; idx += 256) {
        int p = idx >> 4, c4 = idx & 15;
        int r = r0 + p / 14, c = c0 + p % 14;
        *(float4*)(ks + p * KSS + c4 * 4) =
            *(const float4*)(kg + ((size_t)r * WW + c) * EH + c4 * 4);
    }
    for (int idx = tid; idx < 16 * 16; idx += 256) {
        int qi = idx >> 4, c4 = idx & 15;
        int iq = i0 + (qi >> 3), jq = j0 + (qi & 7);
        *(float4*)(qs + qi * 64 + c4 * 4) =
            *(const float4*)(qg + ((size_t)iq * WW + jq) * EH + c4 * 4);
    }
    __syncthreads();

#pragma unroll
    for (int s = 0; s < 2; s++) {
        int qi = warp * 2 + s;
        int di = qi >> 3, dj = qi & 7;
        int iq = i0 + di, jq = j0 + dj;
        int sh = min(max(iq - 3, 0), HH - 7);
        int sw = min(max(jq - 3, 0), WW - 7);
        int offq = (sh - r0) * 14 + (sw - c0);

        int pA = lane;
        int pB = min(lane + 32, 48);
        const float* kA = ks + (offq + (pA / 7) * 14 + pA % 7) * KSS;
        const float* kB = ks + (offq + (pB / 7) * 14 + pB % 7) * KSS;
        const float* qrow = qs + qi * 64;
        unsigned long long a0 = 0ull, a1 = 0ull, b0 = 0ull, b1 = 0ull;
#pragma unroll
        for (int e = 0; e < 64; e += 4) {
            ulonglong2 qp = *(const ulonglong2*)(qrow + e);
            ulonglong2 ka = *(const ulonglong2*)(kA + e);
            ulonglong2 kb = *(const ulonglong2*)(kB + e);
            ffma2(a0, qp.x, ka.x); ffma2(a1, qp.y, ka.y);
            ffma2(b0, qp.x, kb.x); ffma2(b1, qp.y, kb.y);
        }
        float2 uA0 = unpk(a0), uA1 = unpk(a1);
        float2 uB0 = unpk(b0), uB1 = unpk(b1);
        float sA = (uA0.x + uA0.y) + (uA1.x + uA1.y);
        float sB = (lane < 17) ? (uB0.x + uB0.y) + (uB1.x + uB1.y) : -1e30f;

        float mx = fmaxf(sA, sB);
#pragma unroll
        for (int o = 16; o > 0; o >>= 1) mx = fmaxf(mx, __shfl_xor_sync(0xffffffffu, mx, o));
        float eA = __expf(sA - mx);
        float eB = (lane < 17) ? __expf(sB - mx) : 0.f;
        float sum = eA + eB;
#pragma unroll
        for (int o = 16; o > 0; o >>= 1) sum += __shfl_xor_sync(0xffffffffu, sum, o);
        float inv = 1.f / sum;

        as_[qi * ASS + lane] = eA * inv;
        if (lane < 18) as_[qi * ASS + 32 + lane] = eB * inv;
        __syncwarp();

        unsigned long long acc = 0ull;
        const float* vbase = vg + ((size_t)sh * WW + sw) * EH + 2 * lane;
        const float* arow  = as_ + qi * ASS;
#pragma unroll
        for (int p = 0; p < 49; p++) {
            float a = arow[p];
            ffma2(acc, dupf(a),
                  *(const unsigned long long*)(vbase + ((p / 7) * WW + (p % 7)) * EH));
        }
        float2 r = unpk(acc);
        int tok = b * (HH * WW) + iq * WW + jq;
        *(float2*)(g_o + (size_t)tok * DM + h * EH + 2 * lane) = r;
        __syncwarp();
    }
}

// ---------------- launch ----------------
extern "C" void kernel_launch(void* const* d_in, const int* in_sizes, int n_in,
                              void* d_out, int out_size) {
    const float* x      = (const float*)d_in[0];
    const float* pos    = (const float*)d_in[1];
    const float* cond   = (const float*)d_in[2];
    const float* w_norm = (const float*)d_in[3];
    const float* w_qkv  = (const float*)d_in[4];
    const float* w_out  = (const float*)d_in[5];
    float* out = (float*)d_out;

    k_scale<<<NB, 256>>>(cond, w_norm);
    k_rmsfac<<<TOK / 8, 256>>>(x);

    {
        size_t sm_bytes = 128 * 132 * sizeof(float);   // 67584 (Cs superset of As|Bs)
        cudaFuncSetAttribute(k_gemm_qkv_rope,
                             cudaFuncAttributeMaxDynamicSharedMemorySize, (int)sm_bytes);
        dim3 g1((3 * DM) / 128, TOK / 128);            // (6, 36)
        k_gemm_qkv_rope<<<g1, 256, sm_bytes>>>(x, w_qkv, pos);
    }

    {
        size_t sm_bytes = (HALO * KSS + 16 * 64 + 16 * ASS) * sizeof(float); // 37888
        cudaFuncSetAttribute(k_attn,
                             cudaFuncAttributeMaxDynamicSharedMemorySize, (int)sm_bytes);
        dim3 g2(WW / 8, HH / 2, NB * NHEAD);
        k_attn<<<g2, 256, sm_bytes>>>();
    }

    {
        float* go; cudaGetSymbolAddress((void**)&go, g_o);
        size_t sm_bytes = 128 * 68 * sizeof(float);    // 34816 (Cs superset of As|Bs)
        cudaFuncSetAttribute(k_gemm_out,
                             cudaFuncAttributeMaxDynamicSharedMemorySize, (int)sm_bytes);
        dim3 g3(DM / 64, TOK / 128);                   // (4, 36)
        k_gemm_out<<<g3, 256, sm_bytes>>>(go, w_out, x, out);
    }
}

// round 17
// speedup vs baseline: 1.5028x; 1.0212x over previous
#include <cuda_runtime.h>
#include <mma.h>
using namespace nvcuda;

#define TOK   4608      // n*H*W
#define NB    2
#define HH    48
#define WW    48
#define DM    256
#define NHEAD 4
#define EH    64
#define EPS   1e-6f

// ---------------- scratch ----------------
__device__ float g_scale[NB * DM];
__device__ float g_rfac [TOK];
__device__ float g_q   [NB * NHEAD * HH * WW * EH];
__device__ float g_k   [NB * NHEAD * HH * WW * EH];
__device__ float g_v   [NB * NHEAD * HH * WW * EH];
__device__ float g_o   [TOK * DM];

// ---------------- K0: scale[b][c] = dot(cond[b], w_norm[c]) + 1 ----------------
__global__ void k_scale(const float* __restrict__ cond, const float* __restrict__ w_norm) {
    int b = blockIdx.x, c = threadIdx.x;
    const float4* cv = (const float4*)(cond + b * DM);
    const float4* wv = (const float4*)(w_norm + c * DM);
    float s = 0.f;
#pragma unroll 16
    for (int k = 0; k < DM / 4; k++) {
        float4 a = cv[k], w = wv[k];
        s += a.x * w.x + a.y * w.y + a.z * w.z + a.w * w.w;
    }
    g_scale[b * DM + c] = s + 1.f;
}

// ---------------- K1: per-token rsqrt(mean(x^2)+eps) ----------------
__global__ void __launch_bounds__(256) k_rmsfac(const float* __restrict__ x) {
    int warp = threadIdx.x >> 5, lane = threadIdx.x & 31;
    int t = blockIdx.x * 8 + warp;
    const float4* xv = (const float4*)(x + (size_t)t * DM);
    float4 a = xv[lane], b = xv[lane + 32];
    float sq = a.x*a.x + a.y*a.y + a.z*a.z + a.w*a.w
             + b.x*b.x + b.y*b.y + b.z*b.z + b.w*b.w;
#pragma unroll
    for (int o = 16; o > 0; o >>= 1) sq += __shfl_xor_sync(0xffffffffu, sq, o);
    if (lane == 0) g_rfac[t] = rsqrtf(sq * (1.f / DM) + EPS);
}

// ============ qkv GEMM via wmma tf32 (BM=128,BN=128,BK=32) + fused rms + rope ==========
__global__ void __launch_bounds__(256) k_gemm_qkv_rope(const float* __restrict__ X,
                                                       const float* __restrict__ W,
                                                       const float* __restrict__ pos) {
    constexpr int K = DM, LDT = 36, LDC = 132;
    extern __shared__ float smem[];
    float* As = smem;                 // [128][36]
    float* Bs = smem + 128 * LDT;     // [128][36]
    float* Cs = smem;                 // [128][132] (reused after mainloop)

    int tid = threadIdx.x;
    int m0 = blockIdx.y * 128, n0 = blockIdx.x * 128;
    int warp = tid >> 5;
    int wm = warp >> 2, wn = warp & 3;      // 2 x 4 warp grid; warp tile 64x32

    int row = tid >> 1, colh = (tid & 1) * 16;
    int tokA = m0 + row;
    int bA = tokA / (HH * WW);
    const float* Ag = X + (size_t)tokA * K;
    const float* Sg = g_scale + bA * DM;
    float rfac = g_rfac[tokA];
    const float* Bg = W + (size_t)(n0 + row) * K;

    wmma::fragment<wmma::accumulator, 16, 16, 8, float> cf[4][2];
#pragma unroll
    for (int i = 0; i < 4; i++)
#pragma unroll
        for (int j = 0; j < 2; j++) wmma::fill_fragment(cf[i][j], 0.f);

    for (int kt = 0; kt < K / 32; kt++) {
        int k0 = kt * 32;
        __syncthreads();
#pragma unroll
        for (int c4 = 0; c4 < 4; c4++) {
            float4 v = *(const float4*)(Ag + k0 + colh + c4 * 4);
            float4 s = *(const float4*)(Sg + k0 + colh + c4 * 4);
            *(float4*)(As + row * LDT + colh + c4 * 4) =
                make_float4(v.x*s.x*rfac, v.y*s.y*rfac, v.z*s.z*rfac, v.w*s.w*rfac);
            *(float4*)(Bs + row * LDT + colh + c4 * 4) =
                *(const float4*)(Bg + k0 + colh + c4 * 4);
        }
        __syncthreads();
#pragma unroll
        for (int ks = 0; ks < 4; ks++) {
            int kk = ks * 8;
            wmma::fragment<wmma::matrix_a, 16, 16, 8, wmma::precision::tf32, wmma::row_major> af[4];
            wmma::fragment<wmma::matrix_b, 16, 16, 8, wmma::precision::tf32, wmma::col_major> bf[2];
#pragma unroll
            for (int i = 0; i < 4; i++) {
                wmma::load_matrix_sync(af[i], As + (wm * 64 + i * 16) * LDT + kk, LDT);
#pragma unroll
                for (int t = 0; t < af[i].num_elements; t++)
                    af[i].x[t] = wmma::__float_to_tf32(af[i].x[t]);
            }
#pragma unroll
            for (int j = 0; j < 2; j++) {
                wmma::load_matrix_sync(bf[j], Bs + (wn * 32 + j * 16) * LDT + kk, LDT);
#pragma unroll
                for (int t = 0; t < bf[j].num_elements; t++)
                    bf[j].x[t] = wmma::__float_to_tf32(bf[j].x[t]);
            }
#pragma unroll
            for (int i = 0; i < 4; i++)
#pragma unroll
                for (int j = 0; j < 2; j++)
                    wmma::mma_sync(cf[i][j], af[i], bf[j], cf[i][j]);
        }
    }
    __syncthreads();
#pragma unroll
    for (int i = 0; i < 4; i++)
#pragma unroll
        for (int j = 0; j < 2; j++)
            wmma::store_matrix_sync(Cs + (wm * 64 + i * 16) * LDC + wn * 32 + j * 16,
                                    cf[i][j], LDC, wmma::mem_row_major);
    __syncthreads();

    {
        int r = tid >> 1, half = tid & 1;
        int token = m0 + r;
        int b = token / (HH * WW);
        int ij = token - b * (HH * WW);
        int i = ij / WW, j = ij - i * WW;
        int c_lo = n0 + half * 64;
        int part = c_lo >> 8;            // 0=q 1=k 2=v
        int h = (c_lo & 255) >> 6;
        float* dst = (part == 0 ? g_q : part == 1 ? g_k : g_v)
                   + ((size_t)((b * NHEAD + h) * HH + i) * WW + j) * EH;
        const float* src = Cs + r * LDC + half * 64;

        if (part == 2) {
#pragma unroll
            for (int e4 = 0; e4 < 16; e4++)
                *(float4*)(dst + e4 * 4) = *(const float4*)(src + e4 * 4);
        } else {
            float gh = pos[(i * WW + j) * 2 + 0];
            float gw = pos[(i * WW + j) * 2 + 1];
            float ov[32];
#pragma unroll
            for (int e = 0; e < 16; e++) {
                float f  = 3.14159265358979323846f * exp10f((float)(e & 7) * 0.125f);
                float p  = (e < 8) ? gh : gw;
                float an = p * f;
                float cs = cosf(an), sn = sinf(an);
                float x1 = src[e], x2 = src[e + 16];
                ov[e]      = x1 * cs - x2 * sn;
                ov[e + 16] = x2 * cs + x1 * sn;
            }
            float sc = (part == 0) ? 0.125f : 1.f;
#pragma unroll
            for (int e4 = 0; e4 < 8; e4++)
                *(float4*)(dst + e4 * 4) = make_float4(ov[e4*4]*sc, ov[e4*4+1]*sc,
                                                       ov[e4*4+2]*sc, ov[e4*4+3]*sc);
#pragma unroll
            for (int e4 = 8; e4 < 16; e4++) {
                float4 v = *(const float4*)(src + e4 * 4);
                *(float4*)(dst + e4 * 4) = make_float4(v.x*sc, v.y*sc, v.z*sc, v.w*sc);
            }
        }
    }
}

// ============ out GEMM via wmma tf32 (BM=128,BN=64,BK=32) + skip ==========
__global__ void __launch_bounds__(256) k_gemm_out(const float* __restrict__ A,
                                                  const float* __restrict__ W,
                                                  const float* __restrict__ Sk,
                                                  float* __restrict__ C) {
    constexpr int K = DM, N = DM, LDT = 36, LDC = 68;
    extern __shared__ float smem[];
    float* As = smem;                 // [128][36]
    float* Bs = smem + 128 * LDT;     // [64][36]
    float* Cs = smem;                 // [128][68] (reused)

    int tid = threadIdx.x;
    int m0 = blockIdx.y * 128, n0 = blockIdx.x * 64;
    int warp = tid >> 5;
    int wm = warp >> 1, wn = warp & 1;      // 4 x 2 warp grid; warp tile 32x32

    int arow = tid >> 1, acolh = (tid & 1) * 16;
    const float* Ag = A + (size_t)(m0 + arow) * K;
    int brow = tid >> 2, bcolh = (tid & 3) * 8;
    const float* Bg = W + (size_t)(n0 + brow) * K;

    wmma::fragment<wmma::accumulator, 16, 16, 8, float> cf[2][2];
#pragma unroll
    for (int i = 0; i < 2; i++)
#pragma unroll
        for (int j = 0; j < 2; j++) wmma::fill_fragment(cf[i][j], 0.f);

    for (int kt = 0; kt < K / 32; kt++) {
        int k0 = kt * 32;
        __syncthreads();
#pragma unroll
        for (int c4 = 0; c4 < 4; c4++)
            *(float4*)(As + arow * LDT + acolh + c4 * 4) =
                *(const float4*)(Ag + k0 + acolh + c4 * 4);
#pragma unroll
        for (int c4 = 0; c4 < 2; c4++)
            *(float4*)(Bs + brow * LDT + bcolh + c4 * 4) =
                *(const float4*)(Bg + k0 + bcolh + c4 * 4);
        __syncthreads();
#pragma unroll
        for (int ks = 0; ks < 4; ks++) {
            int kk = ks * 8;
            wmma::fragment<wmma::matrix_a, 16, 16, 8, wmma::precision::tf32, wmma::row_major> af[2];
            wmma::fragment<wmma::matrix_b, 16, 16, 8, wmma::precision::tf32, wmma::col_major> bf[2];
#pragma unroll
            for (int i = 0; i < 2; i++) {
                wmma::load_matrix_sync(af[i], As + (wm * 32 + i * 16) * LDT + kk, LDT);
#pragma unroll
                for (int t = 0; t < af[i].num_elements; t++)
                    af[i].x[t] = wmma::__float_to_tf32(af[i].x[t]);
            }
#pragma unroll
            for (int j = 0; j < 2; j++) {
                wmma::load_matrix_sync(bf[j], Bs + (wn * 32 + j * 16) * LDT + kk, LDT);
#pragma unroll
                for (int t = 0; t < bf[j].num_elements; t++)
                    bf[j].x[t] = wmma::__float_to_tf32(bf[j].x[t]);
            }
#pragma unroll
            for (int i = 0; i < 2; i++)
#pragma unroll
                for (int j = 0; j < 2; j++)
                    wmma::mma_sync(cf[i][j], af[i], bf[j], cf[i][j]);
        }
    }
    __syncthreads();
#pragma unroll
    for (int i = 0; i < 2; i++)
#pragma unroll
        for (int j = 0; j < 2; j++)
            wmma::store_matrix_sync(Cs + (wm * 32 + i * 16) * LDC + wn * 32 + j * 16,
                                    cf[i][j], LDC, wmma::mem_row_major);
    __syncthreads();

    {
        int r = tid >> 1, half = tid & 1;
        int m = m0 + r, nn = n0 + half * 32;
        const float* src = Cs + r * LDC + half * 32;
#pragma unroll
        for (int c4 = 0; c4 < 8; c4++) {
            float4 v = *(const float4*)(src + c4 * 4);
            float4 s = *(const float4*)&Sk[(size_t)m * N + nn + c4 * 4];
            *(float4*)&C[(size_t)m * N + nn + c4 * 4] =
                make_float4(v.x + s.x, v.y + s.y, v.z + s.z, v.w + s.w);
        }
    }
}

// ============ attention v6: full tensor-core (tf32 wmma) ==========
// Block = 2x8 queries, halo 8x14 = 112 positions.
//   S[16,112] = Q[16,64] @ K^T   (7 warps x 8 mma)
//   masked softmax (SIMT, probs written back as tf32)
//   O[16,64]  = P[16,112] @ V    (4 warps x 14 mma)
#define KHS 68             // K/V smem row stride (mult of 4)
#define PSS 120            // scores row stride (mult of 8)
#define NPOS 112
__global__ void __launch_bounds__(256) k_attn() {
    extern __shared__ float sm[];
    float* Ks = sm;                        // [112][68]
    float* Vs = sm + NPOS * KHS;           // [112][68]
    float* Qs = sm + 2 * NPOS * KHS;       // [16][68]
    float* Ss = Qs + 16 * KHS;             // [16][120] scores -> probs
    float* Os = Ks;                        // [16][68] (reuse K region)

    int j0 = blockIdx.x * 8;
    int i0 = blockIdx.y * 2;
    int bh = blockIdx.z;
    int b = bh >> 2, h = bh & 3;
    int tid = threadIdx.x;
    int warp = tid >> 5, lane = tid & 31;

    int r0 = min(max(i0 - 3, 0), HH - 8);
    int c0 = min(max(j0 - 3, 0), WW - 14);

    const float* kg = g_k + (size_t)(b * NHEAD + h) * HH * WW * EH;
    const float* vg = g_v + (size_t)(b * NHEAD + h) * HH * WW * EH;
    const float* qg = g_q + (size_t)(b * NHEAD + h) * HH * WW * EH;

    // fill K,V halo + Q, converting to tf32
    for (int idx = tid; idx < NPOS * 16; idx += 256) {
        int p = idx >> 4, c4 = idx & 15;
        int r = r0 + p / 14, c = c0 + p % 14;
        size_t go = ((size_t)r * WW + c) * EH + c4 * 4;
        float4 kv = *(const float4*)(kg + go);
        float4 vv = *(const float4*)(vg + go);
        *(float4*)(Ks + p * KHS + c4 * 4) = make_float4(
            wmma::__float_to_tf32(kv.x), wmma::__float_to_tf32(kv.y),
            wmma::__float_to_tf32(kv.z), wmma::__float_to_tf32(kv.w));
        *(float4*)(Vs + p * KHS + c4 * 4) = make_float4(
            wmma::__float_to_tf32(vv.x), wmma::__float_to_tf32(vv.y),
            wmma::__float_to_tf32(vv.z), wmma::__float_to_tf32(vv.w));
    }
    for (int idx = tid; idx < 16 * 16; idx += 256) {
        int qi = idx >> 4, c4 = idx & 15;
        int iq = i0 + (qi >> 3), jq = j0 + (qi & 7);
        float4 qv = *(const float4*)(qg + ((size_t)iq * WW + jq) * EH + c4 * 4);
        *(float4*)(Qs + qi * KHS + c4 * 4) = make_float4(
            wmma::__float_to_tf32(qv.x), wmma::__float_to_tf32(qv.y),
            wmma::__float_to_tf32(qv.z), wmma::__float_to_tf32(qv.w));
    }
    __syncthreads();

    // QK: warp w < 7 computes S[:, w*16 .. w*16+15]
    if (warp < 7) {
        int pt = warp * 16;
        wmma::fragment<wmma::accumulator, 16, 16, 8, float> cf;
        wmma::fill_fragment(cf, 0.f);
#pragma unroll
        for (int ks = 0; ks < 8; ks++) {
            wmma::fragment<wmma::matrix_a, 16, 16, 8, wmma::precision::tf32, wmma::row_major> af;
            wmma::fragment<wmma::matrix_b, 16, 16, 8, wmma::precision::tf32, wmma::col_major> bf;
            wmma::load_matrix_sync(af, Qs + ks * 8, KHS);
            wmma::load_matrix_sync(bf, Ks + pt * KHS + ks * 8, KHS);
            wmma::mma_sync(cf, af, bf, cf);
        }
        wmma::store_matrix_sync(Ss + pt, cf, PSS, wmma::mem_row_major);
    }
    __syncthreads();

    // masked softmax: warp handles 2 queries; lane covers idx, idx+32, idx+64, idx+96
#pragma unroll
    for (int s = 0; s < 2; s++) {
        int qi = warp * 2 + s;
        int iq = i0 + (qi >> 3), jq = j0 + (qi & 7);
        int rlo = min(max(iq - 3, 0), HH - 7) - r0;
        int clo = min(max(jq - 3, 0), WW - 7) - c0;
        float* srow = Ss + qi * PSS;

        float v[4];
        bool ok[4];
#pragma unroll
        for (int u = 0; u < 4; u++) {
            int idx = lane + u * 32;
            bool inb = idx < NPOS;
            int pr = idx / 14, pc = idx - pr * 14;
            bool val = inb && (pr >= rlo) && (pr < rlo + 7) && (pc >= clo) && (pc < clo + 7);
            ok[u] = val;
            v[u] = val ? srow[idx] : -1e30f;
        }
        float mx = fmaxf(fmaxf(v[0], v[1]), fmaxf(v[2], v[3]));
#pragma unroll
        for (int o = 16; o > 0; o >>= 1) mx = fmaxf(mx, __shfl_xor_sync(0xffffffffu, mx, o));
        float e[4], sum = 0.f;
#pragma unroll
        for (int u = 0; u < 4; u++) { e[u] = ok[u] ? __expf(v[u] - mx) : 0.f; sum += e[u]; }
#pragma unroll
        for (int o = 16; o > 0; o >>= 1) sum += __shfl_xor_sync(0xffffffffu, sum, o);
        float inv = 1.f / sum;
#pragma unroll
        for (int u = 0; u < 4; u++) {
            int idx = lane + u * 32;
            if (idx < PSS) srow[idx] = (idx < NPOS) ? wmma::__float_to_tf32(e[u] * inv) : 0.f;
        }
    }
    __syncthreads();

    // AV: warp w < 4 computes O[:, w*16 .. w*16+15]
    if (warp < 4) {
        int et = warp * 16;
        wmma::fragment<wmma::accumulator, 16, 16, 8, float> cf;
        wmma::fill_fragment(cf, 0.f);
#pragma unroll
        for (int ks = 0; ks < 14; ks++) {
            wmma::fragment<wmma::matrix_a, 16, 16, 8, wmma::precision::tf32, wmma::row_major> af;
            wmma::fragment<wmma::matrix_b, 16, 16, 8, wmma::precision::tf32, wmma::row_major> bf;
            wmma::load_matrix_sync(af, Ss + ks * 8, PSS);
            wmma::load_matrix_sync(bf, Vs + ks * 8 * KHS + et, KHS);
            wmma::mma_sync(cf, af, bf, cf);
        }
        wmma::store_matrix_sync(Os + et, cf, KHS, wmma::mem_row_major);
    }
    __syncthreads();

    // write out: 16 q x 64 e, 4 floats per thread
    {
        int qi = tid >> 4, c4 = tid & 15;
        int iq = i0 + (qi >> 3), jq = j0 + (qi & 7);
        int tok = b * (HH * WW) + iq * WW + jq;
        *(float4*)(g_o + (size_t)tok * DM + h * EH + c4 * 4) =
            *(const float4*)(Os + qi * KHS + c4 * 4);
    }
}

// ---------------- launch ----------------
extern "C" void kernel_launch(void* const* d_in, const int* in_sizes, int n_in,
                              void* d_out, int out_size) {
    const float* x      = (const float*)d_in[0];
    const float* pos    = (const float*)d_in[1];
    const float* cond   = (const float*)d_in[2];
    const float* w_norm = (const float*)d_in[3];
    const float* w_qkv  = (const float*)d_in[4];
    const float* w_out  = (const float*)d_in[5];
    float* out = (float*)d_out;

    k_scale<<<NB, 256>>>(cond, w_norm);
    k_rmsfac<<<TOK / 8, 256>>>(x);

    {
        size_t sm_bytes = 128 * 132 * sizeof(float);   // 67584
        cudaFuncSetAttribute(k_gemm_qkv_rope,
                             cudaFuncAttributeMaxDynamicSharedMemorySize, (int)sm_bytes);
        dim3 g1((3 * DM) / 128, TOK / 128);            // (6, 36)
        k_gemm_qkv_rope<<<g1, 256, sm_bytes>>>(x, w_qkv, pos);
    }

    {
        size_t sm_bytes = (2 * NPOS * KHS + 16 * KHS + 16 * PSS) * sizeof(float); // 72960
        cudaFuncSetAttribute(k_attn,
                             cudaFuncAttributeMaxDynamicSharedMemorySize, (int)sm_bytes);
        dim3 g2(WW / 8, HH / 2, NB * NHEAD);
        k_attn<<<g2, 256, sm_bytes>>>();
    }

    {
        float* go; cudaGetSymbolAddress((void**)&go, g_o);
        size_t sm_bytes = 128 * 68 * sizeof(float);    // 34816
        cudaFuncSetAttribute(k_gemm_out,
                             cudaFuncAttributeMaxDynamicSharedMemorySize, (int)sm_bytes);
        dim3 g3(DM / 64, TOK / 128);                   // (4, 36)
        k_gemm_out<<<g3, 256, sm_bytes>>>(go, w_out, x, out);
    }
}